// round 3
// baseline (speedup 1.0000x reference)
#include <cuda_runtime.h>
#include <math.h>

#define BATCH 2
#define NPTS  8192
#define IC    64
#define OC    128
#define KNN   16
#define NROWS (BATCH*NPTS)      /* 16384 */
#define EPSF  1e-5f

/* ---------------- scratch (no allocations allowed) ---------------- */
__device__ int   g_knn[NROWS*KNN];     /* 1 MB  : global row indices of 16 NN */
__device__ float g_ypre[NROWS*OC];     /* 8 MB  : pre-BN activations */
__device__ float g_part[64*OC*2];      /* 64 KB : BN partial sums */
__device__ float g_mu[OC];
__device__ float g_rstd[OC];

__device__ __forceinline__ float gelu_f(float x){
    return 0.5f*x*(1.0f + erff(x*0.70710678118654752440f));
}

/* ================= K1: brute-force KNN (thread per query) ================= */
#define K1_THREADS 128
#define TILE_C     1024

__global__ void __launch_bounds__(K1_THREADS)
knn_kernel(const float* __restrict__ pts)
{
    __shared__ float4 tile[TILE_C];
    const int q     = blockIdx.x * K1_THREADS + threadIdx.x;  /* 0..16383 */
    const int cbase = (q >> 13) << 13;                        /* batch base row */

    const float qx = pts[q*3+0], qy = pts[q*3+1], qz = pts[q*3+2];
    const float qs = qx*qx + qy*qy + qz*qz;

    float kd[KNN]; int ki[KNN];
#pragma unroll
    for (int s = 0; s < KNN; s++){ kd[s] = 3.4e38f; ki[s] = cbase; }

    for (int t0 = 0; t0 < NPTS; t0 += TILE_C){
        __syncthreads();
        for (int t = threadIdx.x; t < TILE_C; t += K1_THREADS){
            const int j = cbase + t0 + t;
            float x = pts[j*3+0], y = pts[j*3+1], z = pts[j*3+2];
            tile[t] = make_float4(x, y, z, x*x + y*y + z*z);
        }
        __syncthreads();

        float kmax = kd[KNN-1];
#pragma unroll 4
        for (int j = 0; j < TILE_C; j++){
            const float4 c = tile[j];
            float dot = qx*c.x + qy*c.y + qz*c.z;
            float d2  = fmaf(-2.0f, dot, qs + c.w);   /* matches ref formula */
            if (d2 < kmax){
                int jj = cbase + t0 + j;
#pragma unroll
                for (int s = 0; s < KNN; s++){        /* sorted insert (bubble) */
                    bool  lt = d2 < kd[s];
                    float od = kd[s]; int oi = ki[s];
                    kd[s] = lt ? d2 : od;  ki[s] = lt ? jj : oi;
                    d2    = lt ? od : d2;  jj    = lt ? oi : jj;
                }
                kmax = kd[KNN-1];
            }
        }
    }
#pragma unroll
    for (int s = 0; s < KNN; s++) g_knn[q*KNN + s] = ki[s];
}

/* ====== K2: gather-mean -> fc1/GELU/LN1 -> fc2/GELU/LN2 -> dw -> pw ====== */
#define K2_THREADS 256
#define RT         16
#define NTILES     (NROWS/RT)    /* 1024 */

/* dynamic smem layout (floats) */
#define OFF_W1   0
#define OFF_W2   (OFF_W1 + 64*128)
#define OFF_PWT  (OFF_W2 + 128*128)
#define OFF_X    (OFF_PWT + 128*129)   /* padded transpose of pw_w */
#define OFF_H    (OFF_X + RT*64)
#define OFF_H2   (OFF_H + RT*128)
#define SMEM_K2_FLOATS (OFF_H2 + RT*128)
#define SMEM_K2_BYTES  (SMEM_K2_FLOATS*4)   /* 184832 B */

__device__ __forceinline__ void ln_rows(float* buf, const float* __restrict__ g,
                                        const float* __restrict__ b,
                                        const float* __restrict__ sw,
                                        const float* __restrict__ sb, int tid)
{
    const int wid = tid >> 5, lane = tid & 31;
#pragma unroll
    for (int rr = 0; rr < 2; rr++){
        const int r = wid*2 + rr;
        float v0 = buf[r*128 +       lane];
        float v1 = buf[r*128 +  32 + lane];
        float v2 = buf[r*128 +  64 + lane];
        float v3 = buf[r*128 +  96 + lane];
        float s  = v0+v1+v2+v3;
        float s2 = v0*v0 + v1*v1 + v2*v2 + v3*v3;
#pragma unroll
        for (int o = 16; o > 0; o >>= 1){
            s  += __shfl_xor_sync(0xffffffffu, s,  o);
            s2 += __shfl_xor_sync(0xffffffffu, s2, o);
        }
        const float mu   = s  * (1.0f/128.0f);
        const float var  = s2 * (1.0f/128.0f) - mu*mu;
        const float rstd = rsqrtf(var + EPSF);
#pragma unroll
        for (int qq = 0; qq < 4; qq++){
            const int c = qq*32 + lane;
            float v  = (qq==0)?v0:(qq==1)?v1:(qq==2)?v2:v3;
            float nv = (v - mu)*rstd*g[c] + b[c];
            if (sw) nv = nv*sw[c] + sb[c];
            buf[r*128 + c] = nv;
        }
    }
}

extern __shared__ float smem[];

__global__ void __launch_bounds__(K2_THREADS)
mlp_kernel(const float* __restrict__ feats,
           const float* __restrict__ fc1_w, const float* __restrict__ fc1_b,
           const float* __restrict__ ln1_g, const float* __restrict__ ln1_b,
           const float* __restrict__ fc2_w, const float* __restrict__ fc2_b,
           const float* __restrict__ ln2_g, const float* __restrict__ ln2_b,
           const float* __restrict__ dw_w,  const float* __restrict__ dw_b,
           const float* __restrict__ pw_w,  const float* __restrict__ pw_b)
{
    float* sW1  = smem + OFF_W1;
    float* sW2  = smem + OFF_W2;
    float* sPWt = smem + OFF_PWT;
    float* sx   = smem + OFF_X;
    float* sh   = smem + OFF_H;
    float* sh2  = smem + OFF_H2;

    const int tid = threadIdx.x;
    for (int i = tid; i < 64*128;  i += K2_THREADS) sW1[i] = fc1_w[i];
    for (int i = tid; i < 128*128; i += K2_THREADS) sW2[i] = fc2_w[i];
    for (int i = tid; i < 128*128; i += K2_THREADS){
        int o = i >> 7, k = i & 127;
        sPWt[k*129 + o] = pw_w[i];            /* padded -> conflict-free */
    }
    const int o  = tid & 127;
    const int rh = tid >> 7;
    const float bias1 = fc1_b[o], bias2 = fc2_b[o], biasp = pw_b[o];
    __syncthreads();

    for (int tile = blockIdx.x; tile < NTILES; tile += gridDim.x){
        /* ---- gather + mean over 16 neighbors ---- */
        {
            const int r  = tid >> 4, cg = tid & 15;
            const int row = tile*RT + r;
            float4 a = make_float4(0.f,0.f,0.f,0.f);
            const int* kp = &g_knn[row*KNN];
#pragma unroll
            for (int n = 0; n < KNN; n++){
                const int gi = kp[n];
                const float4 f = *reinterpret_cast<const float4*>(&feats[gi*IC + cg*4]);
                a.x += f.x; a.y += f.y; a.z += f.z; a.w += f.w;
            }
            const float inv = 1.0f/16.0f;
            *reinterpret_cast<float4*>(&sx[r*IC + cg*4]) =
                make_float4(a.x*inv, a.y*inv, a.z*inv, a.w*inv);
        }
        __syncthreads();

        /* ---- fc1 + GELU ---- */
        {
            float acc[8];
#pragma unroll
            for (int r = 0; r < 8; r++) acc[r] = bias1;
            for (int k = 0; k < IC; k += 4){
                const float w0 = sW1[(k+0)*128+o], w1 = sW1[(k+1)*128+o];
                const float w2 = sW1[(k+2)*128+o], w3 = sW1[(k+3)*128+o];
#pragma unroll
                for (int r = 0; r < 8; r++){
                    const float4 xv = *reinterpret_cast<const float4*>(&sx[(rh*8+r)*IC + k]);
                    acc[r] = fmaf(xv.x,w0,acc[r]); acc[r] = fmaf(xv.y,w1,acc[r]);
                    acc[r] = fmaf(xv.z,w2,acc[r]); acc[r] = fmaf(xv.w,w3,acc[r]);
                }
            }
#pragma unroll
            for (int r = 0; r < 8; r++) sh[(rh*8+r)*128 + o] = gelu_f(acc[r]);
        }
        __syncthreads();
        ln_rows(sh, ln1_g, ln1_b, (const float*)0, (const float*)0, tid);
        __syncthreads();

        /* ---- fc2 + GELU ---- */
        {
            float acc[8];
#pragma unroll
            for (int r = 0; r < 8; r++) acc[r] = bias2;
            for (int k = 0; k < 128; k += 4){
                const float w0 = sW2[(k+0)*128+o], w1 = sW2[(k+1)*128+o];
                const float w2 = sW2[(k+2)*128+o], w3 = sW2[(k+3)*128+o];
#pragma unroll
                for (int r = 0; r < 8; r++){
                    const float4 xv = *reinterpret_cast<const float4*>(&sh[(rh*8+r)*128 + k]);
                    acc[r] = fmaf(xv.x,w0,acc[r]); acc[r] = fmaf(xv.y,w1,acc[r]);
                    acc[r] = fmaf(xv.z,w2,acc[r]); acc[r] = fmaf(xv.w,w3,acc[r]);
                }
            }
#pragma unroll
            for (int r = 0; r < 8; r++) sh2[(rh*8+r)*128 + o] = gelu_f(acc[r]);
        }
        __syncthreads();
        ln_rows(sh2, ln2_g, ln2_b, dw_w, dw_b, tid);   /* LN2 fused with dw scale */
        __syncthreads();

        /* ---- pointwise conv (y @ pw^T + b) -> ypre ---- */
        {
            float acc[8];
#pragma unroll
            for (int r = 0; r < 8; r++) acc[r] = biasp;
            for (int k = 0; k < 128; k += 4){
                const float w0 = sPWt[(k+0)*129+o], w1 = sPWt[(k+1)*129+o];
                const float w2 = sPWt[(k+2)*129+o], w3 = sPWt[(k+3)*129+o];
#pragma unroll
                for (int r = 0; r < 8; r++){
                    const float4 xv = *reinterpret_cast<const float4*>(&sh2[(rh*8+r)*128 + k]);
                    acc[r] = fmaf(xv.x,w0,acc[r]); acc[r] = fmaf(xv.y,w1,acc[r]);
                    acc[r] = fmaf(xv.z,w2,acc[r]); acc[r] = fmaf(xv.w,w3,acc[r]);
                }
            }
#pragma unroll
            for (int r = 0; r < 8; r++)
                g_ypre[(tile*RT + rh*8 + r)*128 + o] = acc[r];
        }
        __syncthreads();
    }
}

/* ================= K3: deterministic BN stats (two stage) ================= */
__global__ void __launch_bounds__(128) bnstat_kernel(void)
{
    const int c  = threadIdx.x;
    const int r0 = blockIdx.x * 256;
    float s = 0.f, s2 = 0.f;
    for (int r = 0; r < 256; r++){
        const float v = g_ypre[(r0 + r)*128 + c];
        s += v; s2 = fmaf(v, v, s2);
    }
    g_part[(blockIdx.x*128 + c)*2 + 0] = s;
    g_part[(blockIdx.x*128 + c)*2 + 1] = s2;
}

__global__ void __launch_bounds__(128) bnfinal_kernel(void)
{
    const int c = threadIdx.x;
    float s = 0.f, s2 = 0.f;
    for (int b = 0; b < 64; b++){
        s  += g_part[(b*128 + c)*2 + 0];
        s2 += g_part[(b*128 + c)*2 + 1];
    }
    const float mu  = s  * (1.0f/(float)NROWS);
    const float var = s2 * (1.0f/(float)NROWS) - mu*mu;
    g_mu[c]   = mu;
    g_rstd[c] = rsqrtf(var + EPSF);
}

/* ========== K4: BN apply + GELU + residual (feats @ proj_w + b) ========== */
#define K4_THREADS 256
__global__ void __launch_bounds__(K4_THREADS)
out_kernel(const float* __restrict__ feats,
           const float* __restrict__ proj_w, const float* __restrict__ proj_b,
           const float* __restrict__ bn_g,   const float* __restrict__ bn_b,
           float* __restrict__ out)
{
    __shared__ float sproj[64*128];
    __shared__ float sfeat[RT*64];
    const int tid = threadIdx.x;
    for (int i = tid; i < 64*128; i += K4_THREADS) sproj[i] = proj_w[i];
    const int o  = tid & 127;
    const int rh = tid >> 7;
    const float pb = proj_b[o];
    const float mu = g_mu[o], rs = g_rstd[o];
    const float bg = bn_g[o], bb = bn_b[o];
    __syncthreads();

    for (int tile = blockIdx.x; tile < NTILES; tile += gridDim.x){
        __syncthreads();
        for (int i = tid; i < RT*64; i += K4_THREADS)
            sfeat[i] = feats[tile*RT*64 + i];
        __syncthreads();

        float acc[8];
#pragma unroll
        for (int r = 0; r < 8; r++) acc[r] = pb;
        for (int k = 0; k < 64; k += 4){
            const float w0 = sproj[(k+0)*128+o], w1 = sproj[(k+1)*128+o];
            const float w2 = sproj[(k+2)*128+o], w3 = sproj[(k+3)*128+o];
#pragma unroll
            for (int r = 0; r < 8; r++){
                const float4 xv = *reinterpret_cast<const float4*>(&sfeat[(rh*8+r)*64 + k]);
                acc[r] = fmaf(xv.x,w0,acc[r]); acc[r] = fmaf(xv.y,w1,acc[r]);
                acc[r] = fmaf(xv.z,w2,acc[r]); acc[r] = fmaf(xv.w,w3,acc[r]);
            }
        }
#pragma unroll
        for (int r = 0; r < 8; r++){
            const int row = tile*RT + rh*8 + r;
            const float yv = g_ypre[row*128 + o];
            const float yn = (yv - mu)*rs*bg + bb;
            out[row*128 + o] = gelu_f(yn) + acc[r];
        }
    }
}

/* ============================ launcher ============================ */
extern "C" void kernel_launch(void* const* d_in, const int* in_sizes, int n_in,
                              void* d_out, int out_size)
{
    const float* pts    = (const float*)d_in[0];
    const float* feats  = (const float*)d_in[1];
    const float* fc1_w  = (const float*)d_in[2];
    const float* fc1_b  = (const float*)d_in[3];
    const float* ln1_g  = (const float*)d_in[4];
    const float* ln1_b  = (const float*)d_in[5];
    const float* fc2_w  = (const float*)d_in[6];
    const float* fc2_b  = (const float*)d_in[7];
    const float* ln2_g  = (const float*)d_in[8];
    const float* ln2_b  = (const float*)d_in[9];
    const float* dw_w   = (const float*)d_in[10];
    const float* dw_b   = (const float*)d_in[11];
    const float* pw_w   = (const float*)d_in[12];
    const float* pw_b   = (const float*)d_in[13];
    const float* bn_g   = (const float*)d_in[14];
    const float* bn_b   = (const float*)d_in[15];
    const float* proj_w = (const float*)d_in[16];
    const float* proj_b = (const float*)d_in[17];
    float* out = (float*)d_out;

    cudaFuncSetAttribute(mlp_kernel, cudaFuncAttributeMaxDynamicSharedMemorySize,
                         SMEM_K2_BYTES);

    knn_kernel<<<NROWS / K1_THREADS, K1_THREADS>>>(pts);
    mlp_kernel<<<148, K2_THREADS, SMEM_K2_BYTES>>>(feats,
        fc1_w, fc1_b, ln1_g, ln1_b, fc2_w, fc2_b, ln2_g, ln2_b,
        dw_w, dw_b, pw_w, pw_b);
    bnstat_kernel<<<64, 128>>>();
    bnfinal_kernel<<<1, 128>>>();
    out_kernel<<<148, K4_THREADS>>>(feats, proj_w, proj_b, bn_g, bn_b, out);
}

// round 4
// speedup vs baseline: 1.7808x; 1.7808x over previous
#include <cuda_runtime.h>
#include <math.h>

#define BATCH 2
#define NPTS  8192
#define IC    64
#define OC    128
#define KNN   16
#define NROWS (BATCH*NPTS)      /* 16384 */
#define EPSF  1e-5f

#define GSEG  4                 /* KNN candidate segments per query */
#define SEGN  (NPTS/GSEG)       /* 2048 */
#define BCAP  40                /* per-thread pending buffer capacity */
#define BTRIG 32                /* flush trigger (checked every 4 cands) */
#define K2_GRID 148

/* ---------------- scratch (no allocations allowed) ---------------- */
__device__ int   g_knn[NROWS*KNN];          /* 1 MB */
__device__ float g_ypre[NROWS*OC];          /* 8 MB */
__device__ float g_segd[GSEG*KNN*NROWS];    /* 4 MB : per-segment top-16 d2 */
__device__ int   g_segi[GSEG*KNN*NROWS];    /* 4 MB : per-segment top-16 idx */
__device__ float g_part[K2_GRID*OC*2];      /* BN partial sums */
__device__ float g_mu[OC];
__device__ float g_rstd[OC];

__device__ __forceinline__ float gelu_f(float x){
    return 0.5f*x*(1.0f + erff(x*0.70710678118654752440f));
}

/* =============== K1a: segmented KNN with deferred-buffer top-16 =============== */
#define K1_THREADS 128
#define TILE_C     1024

#define FLUSH() do{                                                   \
    for (int t = 0; t < cnt; t++){                                    \
        float d2f = bd[t]; int jj = bi[t];                            \
        _Pragma("unroll")                                             \
        for (int s = 0; s < KNN; s++){                                \
            bool  lt = d2f < kd[s];                                   \
            float od = kd[s]; int oi = ki[s];                         \
            kd[s] = lt ? d2f : od;  ki[s] = lt ? jj : oi;             \
            d2f   = lt ? od  : d2f; jj    = lt ? oi : jj;             \
        }                                                             \
    }                                                                 \
    cnt = 0; kmax = kd[KNN-1];                                        \
}while(0)

__global__ void __launch_bounds__(K1_THREADS)
knn_seg_kernel(const float* __restrict__ pts)
{
    __shared__ float4 tile[TILE_C];
    const int q     = blockIdx.x * K1_THREADS + threadIdx.x;  /* 0..16383 */
    const int seg   = blockIdx.y;                             /* 0..3 */
    const int cbase = (q >> 13) << 13;                        /* batch base row */
    const int sbase = cbase + seg*SEGN;

    const float qx = pts[q*3+0], qy = pts[q*3+1], qz = pts[q*3+2];
    const float qs = qx*qx + qy*qy + qz*qz;

    float kd[KNN]; int ki[KNN];
#pragma unroll
    for (int s = 0; s < KNN; s++){ kd[s] = 3.4e38f; ki[s] = cbase; }

    float bd[BCAP]; int bi[BCAP];     /* local-memory pending buffer */
    int   cnt  = 0;
    float kmax = 3.4e38f;

    for (int t0 = 0; t0 < SEGN; t0 += TILE_C){
        __syncthreads();
        for (int t = threadIdx.x; t < TILE_C; t += K1_THREADS){
            const int j = sbase + t0 + t;
            float x = pts[j*3+0], y = pts[j*3+1], z = pts[j*3+2];
            tile[t] = make_float4(x, y, z, x*x + y*y + z*z);
        }
        __syncthreads();

#pragma unroll 4
        for (int j = 0; j < TILE_C; j++){
            const float4 c = tile[j];
            float dot = qx*c.x + qy*c.y + qz*c.z;            /* same as before */
            float d2  = fmaf(-2.0f, dot, qs + c.w);          /* ref formula    */
            if (d2 < kmax){ bd[cnt] = d2; bi[cnt] = sbase + t0 + j; cnt++; }
            if ((j & 3) == 3){
                if (__any_sync(0xffffffffu, cnt >= BTRIG)) FLUSH();
            }
        }
    }
    FLUSH();

    /* store sorted 16-list; layout coalesced over q */
#pragma unroll
    for (int t = 0; t < KNN; t++){
        g_segd[(seg*KNN + t)*NROWS + q] = kd[t];
        g_segi[(seg*KNN + t)*NROWS + q] = ki[t];
    }
}

/* =============== K1b: 4-way merge of sorted segment lists =============== */
__global__ void __launch_bounds__(256)
knn_merge_kernel(void)
{
    const int q = blockIdx.x*256 + threadIdx.x;
    float dl[GSEG][KNN+1];
    int   il[GSEG][KNN+1];
#pragma unroll
    for (int s = 0; s < GSEG; s++){
#pragma unroll
        for (int t = 0; t < KNN; t++){
            dl[s][t] = g_segd[(s*KNN + t)*NROWS + q];
            il[s][t] = g_segi[(s*KNN + t)*NROWS + q];
        }
        dl[s][KNN] = 3.4e38f; il[s][KNN] = 0x7fffffff;   /* sentinel */
    }
    int p[GSEG] = {0,0,0,0};
#pragma unroll
    for (int r = 0; r < KNN; r++){
        int   bs  = 0;
        float bdv = dl[0][p[0]];
        int   biv = il[0][p[0]];
#pragma unroll
        for (int s = 1; s < GSEG; s++){
            float dv = dl[s][p[s]];
            int   iv = il[s][p[s]];
            bool better = (dv < bdv) || (dv == bdv && iv < biv);
            bs  = better ? s  : bs;
            bdv = better ? dv : bdv;
            biv = better ? iv : biv;
        }
        g_knn[q*KNN + r] = biv;
        p[bs]++;
    }
}

/* ====== K2: gather-mean -> fc1/GELU/LN1 -> fc2/GELU/LN2 -> dw -> pw (+BN stats) ====== */
#define K2_THREADS 256
#define RT         16
#define NTILES     (NROWS/RT)    /* 1024 */

#define OFF_W1   0
#define OFF_W2   (OFF_W1 + 64*128)
#define OFF_PWT  (OFF_W2 + 128*128)
#define OFF_X    (OFF_PWT + 128*129)
#define OFF_H    (OFF_X + RT*64)
#define OFF_H2   (OFF_H + RT*128)
#define SMEM_K2_FLOATS (OFF_H2 + RT*128)
#define SMEM_K2_BYTES  (SMEM_K2_FLOATS*4)   /* 184832 B */

__device__ __forceinline__ void ln_rows(float* buf, const float* __restrict__ g,
                                        const float* __restrict__ b,
                                        const float* __restrict__ sw,
                                        const float* __restrict__ sb, int tid)
{
    const int wid = tid >> 5, lane = tid & 31;
#pragma unroll
    for (int rr = 0; rr < 2; rr++){
        const int r = wid*2 + rr;
        float v0 = buf[r*128 +       lane];
        float v1 = buf[r*128 +  32 + lane];
        float v2 = buf[r*128 +  64 + lane];
        float v3 = buf[r*128 +  96 + lane];
        float s  = v0+v1+v2+v3;
        float s2 = v0*v0 + v1*v1 + v2*v2 + v3*v3;
#pragma unroll
        for (int o = 16; o > 0; o >>= 1){
            s  += __shfl_xor_sync(0xffffffffu, s,  o);
            s2 += __shfl_xor_sync(0xffffffffu, s2, o);
        }
        const float mu   = s  * (1.0f/128.0f);
        const float var  = s2 * (1.0f/128.0f) - mu*mu;
        const float rstd = rsqrtf(var + EPSF);
#pragma unroll
        for (int qq = 0; qq < 4; qq++){
            const int c = qq*32 + lane;
            float v  = (qq==0)?v0:(qq==1)?v1:(qq==2)?v2:v3;
            float nv = (v - mu)*rstd*g[c] + b[c];
            if (sw) nv = nv*sw[c] + sb[c];
            buf[r*128 + c] = nv;
        }
    }
}

extern __shared__ float smem[];

__global__ void __launch_bounds__(K2_THREADS)
mlp_kernel(const float* __restrict__ feats,
           const float* __restrict__ fc1_w, const float* __restrict__ fc1_b,
           const float* __restrict__ ln1_g, const float* __restrict__ ln1_b,
           const float* __restrict__ fc2_w, const float* __restrict__ fc2_b,
           const float* __restrict__ ln2_g, const float* __restrict__ ln2_b,
           const float* __restrict__ dw_w,  const float* __restrict__ dw_b,
           const float* __restrict__ pw_w,  const float* __restrict__ pw_b)
{
    float* sW1  = smem + OFF_W1;
    float* sW2  = smem + OFF_W2;
    float* sPWt = smem + OFF_PWT;
    float* sx   = smem + OFF_X;
    float* sh   = smem + OFF_H;
    float* sh2  = smem + OFF_H2;

    const int tid = threadIdx.x;
    for (int i = tid; i < 64*128;  i += K2_THREADS) sW1[i] = fc1_w[i];
    for (int i = tid; i < 128*128; i += K2_THREADS) sW2[i] = fc2_w[i];
    for (int i = tid; i < 128*128; i += K2_THREADS){
        int o = i >> 7, k = i & 127;
        sPWt[k*129 + o] = pw_w[i];
    }
    const int o  = tid & 127;
    const int rh = tid >> 7;
    const float bias1 = fc1_b[o], bias2 = fc2_b[o], biasp = pw_b[o];
    float bn_s = 0.f, bn_q = 0.f;          /* fused BN stats accumulators */
    __syncthreads();

    for (int tile = blockIdx.x; tile < NTILES; tile += gridDim.x){
        /* ---- gather + mean over 16 neighbors ---- */
        {
            const int r  = tid >> 4, cg = tid & 15;
            const int row = tile*RT + r;
            float4 a = make_float4(0.f,0.f,0.f,0.f);
            const int* kp = &g_knn[row*KNN];
#pragma unroll
            for (int n = 0; n < KNN; n++){
                const int gi = kp[n];
                const float4 f = *reinterpret_cast<const float4*>(&feats[gi*IC + cg*4]);
                a.x += f.x; a.y += f.y; a.z += f.z; a.w += f.w;
            }
            const float inv = 1.0f/16.0f;
            *reinterpret_cast<float4*>(&sx[r*IC + cg*4]) =
                make_float4(a.x*inv, a.y*inv, a.z*inv, a.w*inv);
        }
        __syncthreads();

        /* ---- fc1 + GELU ---- */
        {
            float acc[8];
#pragma unroll
            for (int r = 0; r < 8; r++) acc[r] = bias1;
            for (int k = 0; k < IC; k += 4){
                const float w0 = sW1[(k+0)*128+o], w1 = sW1[(k+1)*128+o];
                const float w2 = sW1[(k+2)*128+o], w3 = sW1[(k+3)*128+o];
#pragma unroll
                for (int r = 0; r < 8; r++){
                    const float4 xv = *reinterpret_cast<const float4*>(&sx[(rh*8+r)*IC + k]);
                    acc[r] = fmaf(xv.x,w0,acc[r]); acc[r] = fmaf(xv.y,w1,acc[r]);
                    acc[r] = fmaf(xv.z,w2,acc[r]); acc[r] = fmaf(xv.w,w3,acc[r]);
                }
            }
#pragma unroll
            for (int r = 0; r < 8; r++) sh[(rh*8+r)*128 + o] = gelu_f(acc[r]);
        }
        __syncthreads();
        ln_rows(sh, ln1_g, ln1_b, (const float*)0, (const float*)0, tid);
        __syncthreads();

        /* ---- fc2 + GELU ---- */
        {
            float acc[8];
#pragma unroll
            for (int r = 0; r < 8; r++) acc[r] = bias2;
            for (int k = 0; k < 128; k += 4){
                const float w0 = sW2[(k+0)*128+o], w1 = sW2[(k+1)*128+o];
                const float w2 = sW2[(k+2)*128+o], w3 = sW2[(k+3)*128+o];
#pragma unroll
                for (int r = 0; r < 8; r++){
                    const float4 xv = *reinterpret_cast<const float4*>(&sh[(rh*8+r)*128 + k]);
                    acc[r] = fmaf(xv.x,w0,acc[r]); acc[r] = fmaf(xv.y,w1,acc[r]);
                    acc[r] = fmaf(xv.z,w2,acc[r]); acc[r] = fmaf(xv.w,w3,acc[r]);
                }
            }
#pragma unroll
            for (int r = 0; r < 8; r++) sh2[(rh*8+r)*128 + o] = gelu_f(acc[r]);
        }
        __syncthreads();
        ln_rows(sh2, ln2_g, ln2_b, dw_w, dw_b, tid);   /* LN2 fused with dw */
        __syncthreads();

        /* ---- pointwise conv -> ypre (+ BN stats in registers) ---- */
        {
            float acc[8];
#pragma unroll
            for (int r = 0; r < 8; r++) acc[r] = biasp;
            for (int k = 0; k < 128; k += 4){
                const float w0 = sPWt[(k+0)*129+o], w1 = sPWt[(k+1)*129+o];
                const float w2 = sPWt[(k+2)*129+o], w3 = sPWt[(k+3)*129+o];
#pragma unroll
                for (int r = 0; r < 8; r++){
                    const float4 xv = *reinterpret_cast<const float4*>(&sh2[(rh*8+r)*128 + k]);
                    acc[r] = fmaf(xv.x,w0,acc[r]); acc[r] = fmaf(xv.y,w1,acc[r]);
                    acc[r] = fmaf(xv.z,w2,acc[r]); acc[r] = fmaf(xv.w,w3,acc[r]);
                }
            }
#pragma unroll
            for (int r = 0; r < 8; r++){
                g_ypre[(tile*RT + rh*8 + r)*128 + o] = acc[r];
                bn_s += acc[r];
                bn_q  = fmaf(acc[r], acc[r], bn_q);
            }
        }
        __syncthreads();
    }

    /* ---- per-block BN partials (deterministic) ---- */
    sh [rh*128 + o] = bn_s;
    sh2[rh*128 + o] = bn_q;
    __syncthreads();
    if (tid < 128){
        g_part[(blockIdx.x*128 + tid)*2 + 0] = sh [tid] + sh [128 + tid];
        g_part[(blockIdx.x*128 + tid)*2 + 1] = sh2[tid] + sh2[128 + tid];
    }
}

/* ================= K3: BN finalize (parallel over 4 groups) ================= */
__global__ void __launch_bounds__(512) bnfinal_kernel(void)
{
    __shared__ float rs[512], rq[512];
    const int tid = threadIdx.x;
    const int c = tid & 127, g = tid >> 7;
    float s = 0.f, s2 = 0.f;
    for (int b = g; b < K2_GRID; b += 4){
        s  += g_part[(b*128 + c)*2 + 0];
        s2 += g_part[(b*128 + c)*2 + 1];
    }
    rs[tid] = s; rq[tid] = s2;
    __syncthreads();
    if (g == 0){
        float S  = rs[c] + rs[128+c] + rs[256+c] + rs[384+c];
        float S2 = rq[c] + rq[128+c] + rq[256+c] + rq[384+c];
        const float mu  = S  * (1.0f/(float)NROWS);
        const float var = S2 * (1.0f/(float)NROWS) - mu*mu;
        g_mu[c]   = mu;
        g_rstd[c] = rsqrtf(var + EPSF);
    }
}

/* ========== K4: BN apply + GELU + residual (feats @ proj_w + b) ========== */
#define K4_THREADS 256
__global__ void __launch_bounds__(K4_THREADS)
out_kernel(const float* __restrict__ feats,
           const float* __restrict__ proj_w, const float* __restrict__ proj_b,
           const float* __restrict__ bn_g,   const float* __restrict__ bn_b,
           float* __restrict__ out)
{
    __shared__ float sproj[64*128];
    __shared__ float sfeat[RT*64];
    const int tid = threadIdx.x;
    for (int i = tid; i < 64*128; i += K4_THREADS) sproj[i] = proj_w[i];
    const int o  = tid & 127;
    const int rh = tid >> 7;
    const float pb = proj_b[o];
    const float mu = g_mu[o], rs = g_rstd[o];
    const float bg = bn_g[o], bb = bn_b[o];
    __syncthreads();

    for (int tile = blockIdx.x; tile < NTILES; tile += gridDim.x){
        __syncthreads();
        for (int i = tid; i < RT*64; i += K4_THREADS)
            sfeat[i] = feats[tile*RT*64 + i];
        __syncthreads();

        float acc[8];
#pragma unroll
        for (int r = 0; r < 8; r++) acc[r] = pb;
        for (int k = 0; k < 64; k += 4){
            const float w0 = sproj[(k+0)*128+o], w1 = sproj[(k+1)*128+o];
            const float w2 = sproj[(k+2)*128+o], w3 = sproj[(k+3)*128+o];
#pragma unroll
            for (int r = 0; r < 8; r++){
                const float4 xv = *reinterpret_cast<const float4*>(&sfeat[(rh*8+r)*64 + k]);
                acc[r] = fmaf(xv.x,w0,acc[r]); acc[r] = fmaf(xv.y,w1,acc[r]);
                acc[r] = fmaf(xv.z,w2,acc[r]); acc[r] = fmaf(xv.w,w3,acc[r]);
            }
        }
#pragma unroll
        for (int r = 0; r < 8; r++){
            const int row = tile*RT + rh*8 + r;
            const float yv = g_ypre[row*128 + o];
            const float yn = (yv - mu)*rs*bg + bb;
            out[row*128 + o] = gelu_f(yn) + acc[r];
        }
    }
}

/* ============================ launcher ============================ */
extern "C" void kernel_launch(void* const* d_in, const int* in_sizes, int n_in,
                              void* d_out, int out_size)
{
    const float* pts    = (const float*)d_in[0];
    const float* feats  = (const float*)d_in[1];
    const float* fc1_w  = (const float*)d_in[2];
    const float* fc1_b  = (const float*)d_in[3];
    const float* ln1_g  = (const float*)d_in[4];
    const float* ln1_b  = (const float*)d_in[5];
    const float* fc2_w  = (const float*)d_in[6];
    const float* fc2_b  = (const float*)d_in[7];
    const float* ln2_g  = (const float*)d_in[8];
    const float* ln2_b  = (const float*)d_in[9];
    const float* dw_w   = (const float*)d_in[10];
    const float* dw_b   = (const float*)d_in[11];
    const float* pw_w   = (const float*)d_in[12];
    const float* pw_b   = (const float*)d_in[13];
    const float* bn_g   = (const float*)d_in[14];
    const float* bn_b   = (const float*)d_in[15];
    const float* proj_w = (const float*)d_in[16];
    const float* proj_b = (const float*)d_in[17];
    float* out = (float*)d_out;

    cudaFuncSetAttribute(mlp_kernel, cudaFuncAttributeMaxDynamicSharedMemorySize,
                         SMEM_K2_BYTES);

    dim3 g1(NROWS / K1_THREADS, GSEG);
    knn_seg_kernel<<<g1, K1_THREADS>>>(pts);
    knn_merge_kernel<<<NROWS/256, 256>>>();
    mlp_kernel<<<K2_GRID, K2_THREADS, SMEM_K2_BYTES>>>(feats,
        fc1_w, fc1_b, ln1_g, ln1_b, fc2_w, fc2_b, ln2_g, ln2_b,
        dw_w, dw_b, pw_w, pw_b);
    bnfinal_kernel<<<1, 512>>>();
    out_kernel<<<148, K4_THREADS>>>(feats, proj_w, proj_b, bn_g, bn_b, out);
}